// round 14
// baseline (speedup 1.0000x reference)
#include <cuda_runtime.h>
#include <math.h>
#include <limits.h>

#define N_USER 20000
#define N_ITEM 20000
#define NN     40000
#define DD     128
#define HH     4
#define LLAYERS 2
#define MMEM   8
#define TREL   5
#define E_UI_C 40000
#define E_T_C  16000
#define FEPS   1e-5f

#define BK  16
#define LDT 136   // smem row stride; 136 % 32 == 8 -> frag LDS and staging STS conflict-free

// ---------------- device scratch (no cudaMalloc allowed) ----------------
__device__ float g_emb[2L * NN * DD];                 // layers 1,2 (layer0 = input)
__device__ float g_fc[(long)NN * HH * DD];            // combined fc output (users;items)
__device__ float g_rst[(long)N_USER * HH * DD];       // GAT aggregation
__device__ float g_trans[(long)NN * DD];
__device__ float g_el[N_USER * HH];
__device__ float g_er[N_USER * HH];
__device__ int   g_emax[N_USER * HH];
__device__ float g_denom[N_USER * HH];
__device__ float g_e[E_UI_C * HH];
__device__ float g_ex[E_UI_C * HH];
__device__ float g_agg[(long)NN * DD];
__device__ float g_cnt[NN];
__device__ float g_coef[(long)TREL * E_T_C * MMEM];
__device__ float g_ncoef[(long)NN * MMEM];
__device__ float g_nodemem[(long)NN * DD];                  // node-memory direct result
__device__ float g_w2rel [(long)LLAYERS * TREL * DD * MMEM * DD];  // [l,t][o][m,i]
__device__ float g_w2node[(long)LLAYERS * DD * MMEM * DD];         // [l][o][m,i]

// ---------------- helpers ----------------
__device__ __forceinline__ float lrelu(float x) { return x > 0.f ? x : 0.2f * x; }
__device__ __forceinline__ float eluf(float x)  { return x > 0.f ? x : expm1f(x); }
__device__ __forceinline__ int   encf(float f)  { int i = __float_as_int(f); return i >= 0 ? i : (i ^ 0x7FFFFFFF); }
__device__ __forceinline__ float decf(int i)    { return __int_as_float(i >= 0 ? i : (i ^ 0x7FFFFFFF)); }

__device__ __forceinline__ unsigned f2tf(float x) {
    unsigned u;
    asm("cvt.rna.tf32.f32 %0, %1;" : "=r"(u) : "f"(x));
    return u;
}

__device__ __forceinline__ void mma8(float* d, const unsigned* a, const unsigned* b) {
    asm("mma.sync.aligned.m16n8k8.row.col.f32.tf32.tf32.f32 "
        "{%0,%1,%2,%3}, {%4,%5,%6,%7}, {%8,%9}, {%0,%1,%2,%3};"
        : "+f"(d[0]), "+f"(d[1]), "+f"(d[2]), "+f"(d[3])
        : "r"(a[0]), "r"(a[1]), "r"(a[2]), "r"(a[3]), "r"(b[0]), "r"(b[1]));
}

// repack [Z][M=8][O=128][I=128] -> [Z][O=128][M=8,I=128] (row length 1024, k = m*128+i)
__global__ void repack_kernel(const float* __restrict__ in, float* __restrict__ out, long total) {
    long idx = (long)blockIdx.x * 256 + threadIdx.x;
    if (idx >= total) return;
    int i = idx & 127;
    long t1 = idx >> 7;
    int o = t1 & 127;
    long t2 = t1 >> 7;
    int m = t2 & 7;
    long zt = t2 >> 3;
    out[(zt * 128 + o) * 1024 + m * 128 + i] = in[idx];
}

// ---------------- 3xTF32 tensor-core GEMM: C = act(A[M,K] @ B[N,K]^T) ----------------
// Block tile 128x128xBK16; 8 warps = 2(m) x 4(n); warp tile 64x32 (4x4 m16n8k8 atoms).
// In-loop hi/lo split into 4 smem arrays; fragments cached in regs across the 3 passes.
// ACT: 0 plain, 1 elu(x + colBias), 2 plain store + fused attention dot (head = blockIdx.x),
//      3 atomic scatter-add rows into g_agg via dstIdx + count into g_cnt (no C store).
// ATR: elu(a + aBias[k]) applied to A during load. GATHER: row-gather A via gidx.
// EXPAND: A[row,k=(m,i)] = aScale[(z*Mm+row)*8+m] * Araw[gather(row)*128 + i] (K = 1024).
template<int ACT, int ATR, int GATHER, int EXPAND>
__global__ void __launch_bounds__(256, 2) gemm_tc(
    const float* __restrict__ A, int lda,
    const float* __restrict__ B, long strideB,
    float* __restrict__ C, int ldc, long strideC,
    const float* __restrict__ colBias,
    const float* __restrict__ aBias,
    const float* __restrict__ attnLo, float* __restrict__ outLo,
    const float* __restrict__ attnHi, float* __restrict__ outHi,
    const int* __restrict__ gidx, int strideIdx,
    const float* __restrict__ aScale,
    const int* __restrict__ dstIdx,
    int Mm, int Nn, int Kk)
{
    __shared__ float sAh[BK * LDT], sAl[BK * LDT], sBh[BK * LDT], sBl[BK * LDT];

    int z = blockIdx.z;
    B += (long)z * strideB;
    if (ACT != 3) C += (long)z * strideC;
    const int* gptr = GATHER ? (gidx + (long)z * strideIdx) : nullptr;

    int tid = threadIdx.x;
    int lane = tid & 31, warp = tid >> 5;
    int warp_m = warp >> 2, warp_n = warp & 3;
    int q = lane >> 2, t4 = lane & 3;
    int row0 = blockIdx.y * 128;
    int col0 = blockIdx.x * 128;

    float acc[4][4][4];
    #pragma unroll
    for (int i = 0; i < 4; i++)
        #pragma unroll
        for (int j = 0; j < 4; j++)
            #pragma unroll
            for (int k = 0; k < 4; k++) acc[i][j][k] = 0.f;

    float4 aR[2], bR[2];

    auto loadG = [&](int k0) {
        #pragma unroll
        for (int i = 0; i < 2; i++) {
            int lin = tid + i * 256;
            int r = lin >> 2, c4 = lin & 3;
            int gr = row0 + r;
            float4 v = make_float4(0.f, 0.f, 0.f, 0.f);
            if (gr < Mm) {
                long ar = GATHER ? (long)gptr[gr] : (long)gr;
                if (EXPAND) {
                    int ii = (k0 & 127) + c4 * 4;
                    v = *reinterpret_cast<const float4*>(&A[ar * 128 + ii]);
                    float sc = aScale[((long)z * Mm + gr) * MMEM + (k0 >> 7)];
                    v.x *= sc; v.y *= sc; v.z *= sc; v.w *= sc;
                } else {
                    v = *reinterpret_cast<const float4*>(&A[ar * lda + k0 + c4 * 4]);
                    if (ATR) {
                        float4 b4 = *reinterpret_cast<const float4*>(&aBias[k0 + c4 * 4]);
                        v.x = eluf(v.x + b4.x); v.y = eluf(v.y + b4.y);
                        v.z = eluf(v.z + b4.z); v.w = eluf(v.w + b4.w);
                    }
                }
            }
            aR[i] = v;
        }
        #pragma unroll
        for (int i = 0; i < 2; i++) {
            int lin = tid + i * 256;
            int r = lin >> 2, c4 = lin & 3;
            bR[i] = *reinterpret_cast<const float4*>(&B[(long)(col0 + r) * Kk + k0 + c4 * 4]);
        }
    };
    auto storeS = [&]() {
        #pragma unroll
        for (int i = 0; i < 2; i++) {
            int lin = tid + i * 256;
            int r = lin >> 2, c4 = lin & 3;
            float va[4] = {aR[i].x, aR[i].y, aR[i].z, aR[i].w};
            float vb[4] = {bR[i].x, bR[i].y, bR[i].z, bR[i].w};
            #pragma unroll
            for (int j = 0; j < 4; j++) {
                int kr = c4 * 4 + j;
                float hi = __uint_as_float(f2tf(va[j]));
                sAh[kr * LDT + r] = hi;
                sAl[kr * LDT + r] = __uint_as_float(f2tf(va[j] - hi));
                float bhi = __uint_as_float(f2tf(vb[j]));
                sBh[kr * LDT + r] = bhi;
                sBl[kr * LDT + r] = __uint_as_float(f2tf(vb[j] - bhi));
            }
        }
    };

    int nk = Kk / BK;
    loadG(0); storeS(); __syncthreads();

    for (int kt = 0; kt < nk; kt++) {
        if (kt + 1 < nk) loadG((kt + 1) * BK);
        #pragma unroll
        for (int k8 = 0; k8 < 2; k8++) {
            int kk = k8 * 8 + t4;
            unsigned bfh[4][2], bfl[4][2];
            #pragma unroll
            for (int na = 0; na < 4; na++) {
                int cw = warp_n * 32 + na * 8 + q;
                bfh[na][0] = __float_as_uint(sBh[kk * LDT + cw]);
                bfh[na][1] = __float_as_uint(sBh[(kk + 4) * LDT + cw]);
                bfl[na][0] = __float_as_uint(sBl[kk * LDT + cw]);
                bfl[na][1] = __float_as_uint(sBl[(kk + 4) * LDT + cw]);
            }
            #pragma unroll
            for (int mp = 0; mp < 2; mp++) {
                unsigned afh[2][4], afl[2][4];
                #pragma unroll
                for (int mi = 0; mi < 2; mi++) {
                    int rw = warp_m * 64 + (mp * 2 + mi) * 16 + q;
                    afh[mi][0] = __float_as_uint(sAh[kk * LDT + rw]);
                    afh[mi][1] = __float_as_uint(sAh[kk * LDT + rw + 8]);
                    afh[mi][2] = __float_as_uint(sAh[(kk + 4) * LDT + rw]);
                    afh[mi][3] = __float_as_uint(sAh[(kk + 4) * LDT + rw + 8]);
                    afl[mi][0] = __float_as_uint(sAl[kk * LDT + rw]);
                    afl[mi][1] = __float_as_uint(sAl[kk * LDT + rw + 8]);
                    afl[mi][2] = __float_as_uint(sAl[(kk + 4) * LDT + rw]);
                    afl[mi][3] = __float_as_uint(sAl[(kk + 4) * LDT + rw + 8]);
                }
                #pragma unroll
                for (int mi = 0; mi < 2; mi++)
                    #pragma unroll
                    for (int na = 0; na < 4; na++) {
                        float* d = acc[mp * 2 + mi][na];
                        mma8(d, afh[mi], bfh[na]);
                        mma8(d, afh[mi], bfl[na]);
                        mma8(d, afl[mi], bfh[na]);
                    }
            }
        }
        __syncthreads();
        if (kt + 1 < nk) { storeS(); __syncthreads(); }
    }

    // ---- epilogue ----
    if (ACT == 3) {
        // scatter-add rows into g_agg via dstIdx; one thread per row counts into g_cnt
        const int* dptr = dstIdx + (long)z * strideIdx;
        #pragma unroll
        for (int ma = 0; ma < 4; ma++) {
            #pragma unroll
            for (int h = 0; h < 2; h++) {
                int r = row0 + warp_m * 64 + ma * 16 + q + 8 * h;
                if (r >= Mm) continue;
                int dd = dptr[r];
                float* base = &g_agg[(long)dd * DD];
                #pragma unroll
                for (int na = 0; na < 4; na++) {
                    int c = warp_n * 32 + na * 8 + t4 * 2;
                    atomicAdd(base + c,     acc[ma][na][2 * h]);
                    atomicAdd(base + c + 1, acc[ma][na][2 * h + 1]);
                }
                if (warp_n == 0 && t4 == 0) atomicAdd(&g_cnt[dd], 1.0f);
            }
        }
        return;
    }

    #pragma unroll
    for (int ma = 0; ma < 4; ma++) {
        #pragma unroll
        for (int h = 0; h < 2; h++) {
            int r = row0 + warp_m * 64 + ma * 16 + q + 8 * h;
            if (r >= Mm) continue;
            #pragma unroll
            for (int na = 0; na < 4; na++) {
                int c = col0 + warp_n * 32 + na * 8 + t4 * 2;
                float v0 = acc[ma][na][2 * h], v1 = acc[ma][na][2 * h + 1];
                if (ACT == 1) {
                    v0 = eluf(v0 + colBias[c]);
                    v1 = eluf(v1 + colBias[c + 1]);
                }
                *reinterpret_cast<float2*>(&C[(long)r * ldc + c]) = make_float2(v0, v1);
            }
        }
    }

    // ---- fused attention dot (fc GEMM): cross-warp smem reduce ----
    if (ACT == 2) {
        float* sRed = sAh;
        #pragma unroll
        for (int ma = 0; ma < 4; ma++) {
            #pragma unroll
            for (int h = 0; h < 2; h++) {
                int rl = warp_m * 64 + ma * 16 + q + 8 * h;
                int r = row0 + rl;
                const float* av = (r < N_USER) ? attnLo : attnHi;
                float p = 0.f;
                #pragma unroll
                for (int na = 0; na < 4; na++) {
                    int c = col0 + warp_n * 32 + na * 8 + t4 * 2;
                    p += acc[ma][na][2 * h] * av[c] + acc[ma][na][2 * h + 1] * av[c + 1];
                }
                p += __shfl_xor_sync(0xffffffffu, p, 1);
                p += __shfl_xor_sync(0xffffffffu, p, 2);
                if (t4 == 0) sRed[rl * 4 + warp_n] = p;
            }
        }
        __syncthreads();
        if (tid < 128) {
            int r = row0 + tid;
            if (r < Mm) {
                float p = sRed[tid * 4] + sRed[tid * 4 + 1] + sRed[tid * 4 + 2] + sRed[tid * 4 + 3];
                int head = blockIdx.x;
                if (r < N_USER) outLo[r * HH + head] = p;
                else            outHi[(r - N_USER) * HH + head] = p;
            }
        }
    }
}

// ---------------- small kernels (unchanged, proven) ----------------
__global__ void zero_gat() {
    long i = (long)blockIdx.x * 256 + threadIdx.x;
    if (i < (long)N_USER * 512) g_rst[i] = 0.f;
    if (i < N_USER * HH) { g_emax[i] = INT_MIN; g_denom[i] = 0.f; }
}

__global__ void mem_init() {
    long i = (long)blockIdx.x * 256 + threadIdx.x;
    if (i < (long)NN * DD) g_agg[i] = 0.f;
    if (i < NN) g_cnt[i] = 0.f;
}

__global__ void gat_edge1(const int* __restrict__ s, const int* __restrict__ d) {
    int i = blockIdx.x * blockDim.x + threadIdx.x;
    if (i >= E_UI_C) return;
    int si = s[i], di = d[i];
    #pragma unroll
    for (int h = 0; h < HH; h++) {
        float e = lrelu(g_el[si * HH + h] + g_er[di * HH + h]);
        g_e[i * HH + h] = e;
        atomicMax(&g_emax[di * HH + h], encf(e));
    }
}

__global__ void gat_edge2(const int* __restrict__ d) {
    int i = blockIdx.x * blockDim.x + threadIdx.x;
    if (i >= E_UI_C) return;
    int di = d[i];
    #pragma unroll
    for (int h = 0; h < HH; h++) {
        float v = expf(g_e[i * HH + h] - decf(g_emax[di * HH + h]));
        g_ex[i * HH + h] = v;
        atomicAdd(&g_denom[di * HH + h], v);
    }
}

__global__ void gat_edge3(const int* __restrict__ s, const int* __restrict__ d,
                          const float* __restrict__ fs) {
    int sub = threadIdx.x >> 7;
    int e = blockIdx.x * 2 + sub;
    int t = threadIdx.x & 127;
    int si = s[e], di = d[e];
    int h = t >> 5;
    float a = g_ex[e * HH + h] / g_denom[di * HH + h];
    float4 f = *reinterpret_cast<const float4*>(&fs[(long)si * 512 + t * 4]);
    float* r = &g_rst[(long)di * 512 + t * 4];
    atomicAdd(r + 0, a * f.x); atomicAdd(r + 1, a * f.y);
    atomicAdd(r + 2, a * f.z); atomicAdd(r + 3, a * f.w);
}

__global__ void coef_kernel(const float* __restrict__ feat,
                            const int* __restrict__ idx, int idxStride,
                            const float* __restrict__ Wc, int WcStride,
                            const float* __restrict__ bc, int bcStride,
                            float* __restrict__ out, int count) {
    int z = blockIdx.y;
    __shared__ float sW[MMEM * DD];
    __shared__ float sb[MMEM];
    const float* W = Wc + (long)z * WcStride;
    for (int i = threadIdx.x; i < MMEM * DD; i += 256) sW[i] = W[i];
    if (threadIdx.x < MMEM) sb[threadIdx.x] = bc[z * bcStride + threadIdx.x];
    __syncthreads();
    int warp = threadIdx.x >> 5, lane = threadIdx.x & 31;
    int e = blockIdx.x * 8 + warp;
    if (e >= count) return;
    int node = idx ? idx[(long)z * idxStride + e] : e;
    const float* f = feat + (long)node * DD;
    float fv[4];
    #pragma unroll
    for (int j = 0; j < 4; j++) fv[j] = f[lane * 4 + j];
    #pragma unroll
    for (int m = 0; m < MMEM; m++) {
        float p = 0.f;
        #pragma unroll
        for (int j = 0; j < 4; j++) p += fv[j] * sW[m * DD + lane * 4 + j];
        #pragma unroll
        for (int o = 16; o; o >>= 1) p += __shfl_xor_sync(0xffffffffu, p, o);
        if (lane == 0) out[((long)z * count + e) * MMEM + m] = lrelu(p + sb[m]);
    }
}

// warp per node: LN(agg/cnt)+h_bias + nodemem + leaky + trans -> next emb
__global__ void mem_finalize(const float* __restrict__ lnw, const float* __restrict__ lnb,
                             const float* __restrict__ hb, float* __restrict__ out) {
    int warp = threadIdx.x >> 5, lane = threadIdx.x & 31;
    int n = blockIdx.x * 8 + warp;
    float inv = 1.f / fmaxf(g_cnt[n], 1.f);
    float4 a = *reinterpret_cast<const float4*>(&g_agg[(long)n * DD + lane * 4]);
    a.x *= inv; a.y *= inv; a.z *= inv; a.w *= inv;
    float s = a.x + a.y + a.z + a.w;
    #pragma unroll
    for (int o = 16; o; o >>= 1) s += __shfl_xor_sync(0xffffffffu, s, o);
    float mu = s * (1.f / 128.f);
    float4 dv = make_float4(a.x - mu, a.y - mu, a.z - mu, a.w - mu);
    float vs = dv.x * dv.x + dv.y * dv.y + dv.z * dv.z + dv.w * dv.w;
    #pragma unroll
    for (int o = 16; o; o >>= 1) vs += __shfl_xor_sync(0xffffffffu, vs, o);
    float rs = rsqrtf(vs * (1.f / 128.f) + FEPS);
    float4 w4 = *reinterpret_cast<const float4*>(&lnw[lane * 4]);
    float4 b4 = *reinterpret_cast<const float4*>(&lnb[lane * 4]);
    float4 h4 = *reinterpret_cast<const float4*>(&hb[lane * 4]);
    float4 nm = *reinterpret_cast<const float4*>(&g_nodemem[(long)n * DD + lane * 4]);
    float4 tr = *reinterpret_cast<const float4*>(&g_trans[(long)n * DD + lane * 4]);
    float4 o4;
    o4.x = lrelu(dv.x * rs * w4.x + b4.x + h4.x + nm.x) + tr.x;
    o4.y = lrelu(dv.y * rs * w4.y + b4.y + h4.y + nm.y) + tr.y;
    o4.z = lrelu(dv.z * rs * w4.z + b4.z + h4.z + nm.z) + tr.z;
    o4.w = lrelu(dv.w * rs * w4.w + b4.w + h4.w + nm.w) + tr.w;
    *reinterpret_cast<float4*>(&out[(long)n * DD + lane * 4]) = o4;
}

__global__ void final_ln_kernel(const float* __restrict__ e0,
                                const float* __restrict__ w, const float* __restrict__ b,
                                float* __restrict__ out) {
    int warp = threadIdx.x >> 5, lane = threadIdx.x & 31;
    int n = blockIdx.x * 8 + warp;
    float4 v0 = *reinterpret_cast<const float4*>(&e0[(long)n * DD + lane * 4]);
    float4 v1 = *reinterpret_cast<const float4*>(&g_emb[(long)n * DD + lane * 4]);
    float4 v2 = *reinterpret_cast<const float4*>(&g_emb[(long)NN * DD + (long)n * DD + lane * 4]);
    float s = v0.x + v0.y + v0.z + v0.w + v1.x + v1.y + v1.z + v1.w + v2.x + v2.y + v2.z + v2.w;
    #pragma unroll
    for (int o = 16; o; o >>= 1) s += __shfl_xor_sync(0xffffffffu, s, o);
    float mu = s * (1.f / 384.f);
    float4 d0 = make_float4(v0.x - mu, v0.y - mu, v0.z - mu, v0.w - mu);
    float4 d1 = make_float4(v1.x - mu, v1.y - mu, v1.z - mu, v1.w - mu);
    float4 d2 = make_float4(v2.x - mu, v2.y - mu, v2.z - mu, v2.w - mu);
    float vs = d0.x * d0.x + d0.y * d0.y + d0.z * d0.z + d0.w * d0.w
             + d1.x * d1.x + d1.y * d1.y + d1.z * d1.z + d1.w * d1.w
             + d2.x * d2.x + d2.y * d2.y + d2.z * d2.z + d2.w * d2.w;
    #pragma unroll
    for (int o = 16; o; o >>= 1) vs += __shfl_xor_sync(0xffffffffu, vs, o);
    float r = rsqrtf(vs * (1.f / 384.f) + FEPS);
    long base = (long)n * 384;
    #pragma unroll
    for (int seg = 0; seg < 3; seg++) {
        float4 d = seg == 0 ? d0 : (seg == 1 ? d1 : d2);
        int off = seg * 128 + lane * 4;
        float4 w4 = *reinterpret_cast<const float4*>(&w[off]);
        float4 b4 = *reinterpret_cast<const float4*>(&b[off]);
        float4 o4;
        o4.x = d.x * r * w4.x + b4.x; o4.y = d.y * r * w4.y + b4.y;
        o4.z = d.z * r * w4.z + b4.z; o4.w = d.w * r * w4.w + b4.w;
        *reinterpret_cast<float4*>(&out[base + off]) = o4;
    }
}

// ---------------- host orchestration ----------------
extern "C" void kernel_launch(void* const* d_in, const int* in_sizes, int n_in,
                              void* d_out, int out_size) {
    const float* embedding   = (const float*)d_in[0];
    const float* gat_fc_W    = (const float*)d_in[1];
    const float* gat_attn_l  = (const float*)d_in[2];
    const float* gat_attn_r  = (const float*)d_in[3];
    const float* gat_bias    = (const float*)d_in[4];
    const float* proj_W      = (const float*)d_in[5];
    const float* proj_b      = (const float*)d_in[6];
    const float* mem_rel_Wc  = (const float*)d_in[7];
    const float* mem_rel_bc  = (const float*)d_in[8];
    const float* mem_rel_Ww  = (const float*)d_in[9];
    const float* mem_node_Wc = (const float*)d_in[10];
    const float* mem_node_bc = (const float*)d_in[11];
    const float* mem_node_Ww = (const float*)d_in[12];
    const float* mem_h_bias  = (const float*)d_in[13];
    const float* mem_ln_w    = (const float*)d_in[14];
    const float* mem_ln_b    = (const float*)d_in[15];
    const float* final_ln_w  = (const float*)d_in[16];
    const float* final_ln_b  = (const float*)d_in[17];
    const int*   src_u       = (const int*)d_in[18];
    const int*   dst_i       = (const int*)d_in[19];
    const int*   edge_src    = (const int*)d_in[20];
    const int*   edge_dst    = (const int*)d_in[21];

    float *emb, *fc, *rst, *trans, *el, *er, *coefp, *ncoefp, *nodemem, *w2rel, *w2node;
    cudaGetSymbolAddress((void**)&emb,     g_emb);
    cudaGetSymbolAddress((void**)&fc,      g_fc);
    cudaGetSymbolAddress((void**)&rst,     g_rst);
    cudaGetSymbolAddress((void**)&trans,   g_trans);
    cudaGetSymbolAddress((void**)&el,      g_el);
    cudaGetSymbolAddress((void**)&er,      g_er);
    cudaGetSymbolAddress((void**)&coefp,   g_coef);
    cudaGetSymbolAddress((void**)&ncoefp,  g_ncoef);
    cudaGetSymbolAddress((void**)&nodemem, g_nodemem);
    cudaGetSymbolAddress((void**)&w2rel,   g_w2rel);
    cudaGetSymbolAddress((void**)&w2node,  g_w2node);

    // repack einsum weights once: [Z][m][o][i] -> [Z][o][(m,i)]
    {
        long t1 = (long)LLAYERS * TREL * MMEM * DD * DD;
        repack_kernel<<<(int)((t1 + 255) / 256), 256>>>(mem_rel_Ww, w2rel, t1);
        long t2 = (long)LLAYERS * MMEM * DD * DD;
        repack_kernel<<<(int)((t2 + 255) / 256), 256>>>(mem_node_Ww, w2node, t2);
    }

    for (int l = 0; l < LLAYERS; l++) {
        const float* fl = (l == 0) ? embedding : (emb + (long)(l - 1) * NN * DD);
        float* flout = emb + (long)l * NN * DD;

        for (int s = 0; s < 2; s++) {
            const float* W  = gat_fc_W   + ((long)l * 2 + s) * 512 * 128;
            const float* al = gat_attn_l + ((long)l * 2 + s) * 512;
            const float* ar = gat_attn_r + ((long)l * 2 + s) * 512;
            const float* gb = gat_bias   + ((long)l * 2 + s) * 512;
            const float* pW = proj_W     + ((long)l * 2 + s) * 128 * 512;
            const float* pb = proj_b     + ((long)l * 2 + s) * 128;
            // s=0: src=items(high rows), dst=users(low); s=1: src=users(low), dst=items(high)
            const float* vecLo = (s == 0) ? ar : al;
            float*       outLo = (s == 0) ? er : el;
            const float* vecHi = (s == 0) ? al : ar;
            float*       outHi = (s == 0) ? el : er;
            const int* sidx = (s == 0) ? dst_i : src_u;
            const int* didx = (s == 0) ? src_u : dst_i;
            const float* fsp = (s == 0) ? fc + (long)N_USER * 512 : fc;

            zero_gat<<<(N_USER * 512 + 255) / 256, 256>>>();
            dim3 gfc(4, (NN + 127) / 128, 1);
            gemm_tc<2, 0, 0, 0><<<gfc, 256>>>(fl, DD, W, 0, fc, 512, 0,
                                              nullptr, nullptr,
                                              vecLo, outLo, vecHi, outHi,
                                              nullptr, 0, nullptr, nullptr, NN, 512, DD);
            gat_edge1<<<(E_UI_C + 255) / 256, 256>>>(sidx, didx);
            gat_edge2<<<(E_UI_C + 255) / 256, 256>>>(didx);
            gat_edge3<<<E_UI_C / 2, 256>>>(sidx, didx, fsp);
            float* Cp = trans + (long)s * N_USER * DD;
            dim3 gp(1, (N_USER + 127) / 128, 1);
            gemm_tc<1, 1, 0, 0><<<gp, 256>>>(rst, 512, pW, 0, Cp, DD, 0,
                                             pb, gb,
                                             nullptr, nullptr, nullptr, nullptr,
                                             nullptr, 0, nullptr, nullptr, N_USER, DD, 512);
        }

        // -------- memory layer --------
        mem_init<<<(NN * DD + 255) / 256, 256>>>();
        dim3 gc((E_T_C + 7) / 8, TREL);
        coef_kernel<<<gc, 256>>>(fl, edge_dst, E_T_C,
                                 mem_rel_Wc + (long)l * TREL * MMEM * DD, MMEM * DD,
                                 mem_rel_bc + (long)l * TREL * MMEM, MMEM,
                                 coefp, E_T_C);
        // rel memory: D[e,:] = (coef[e]⊗f[src e]) @ W2^T, scatter-added into agg
        dim3 gr(1, E_T_C / 128, TREL);
        gemm_tc<3, 0, 1, 1><<<gr, 256>>>(fl, DD,
                                         w2rel + (long)l * TREL * DD * MMEM * DD,
                                         (long)DD * MMEM * DD,
                                         nullptr, 0, 0,
                                         nullptr, nullptr,
                                         nullptr, nullptr, nullptr, nullptr,
                                         edge_src, E_T_C, coefp, edge_dst,
                                         E_T_C, DD, MMEM * DD);

        dim3 gnc((NN + 7) / 8, 1);
        coef_kernel<<<gnc, 256>>>(fl, nullptr, 0,
                                  mem_node_Wc + (long)l * MMEM * DD, 0,
                                  mem_node_bc + (long)l * MMEM, 0,
                                  ncoefp, NN);
        // node memory: nodemem[n,:] = (ncoef[n]⊗f[n]) @ W2node^T
        dim3 gn(1, (NN + 127) / 128, 1);
        gemm_tc<0, 0, 0, 1><<<gn, 256>>>(fl, DD,
                                         w2node + (long)l * DD * MMEM * DD, 0,
                                         nodemem, DD, 0,
                                         nullptr, nullptr,
                                         nullptr, nullptr, nullptr, nullptr,
                                         nullptr, 0, ncoefp, nullptr,
                                         NN, DD, MMEM * DD);
        mem_finalize<<<NN / 8, 256>>>(mem_ln_w + l * DD, mem_ln_b + l * DD,
                                      mem_h_bias + l * DD, flout);
    }

    final_ln_kernel<<<NN / 8, 256>>>(embedding, final_ln_w, final_ln_b, (float*)d_out);
}

// round 16
// speedup vs baseline: 1.8337x; 1.8337x over previous
#include <cuda_runtime.h>
#include <math.h>
#include <limits.h>

#define N_USER 20000
#define N_ITEM 20000
#define NN     40000
#define DD     128
#define HH     4
#define LLAYERS 2
#define MMEM   8
#define TREL   5
#define E_UI_C 40000
#define E_T_C  16000
#define FEPS   1e-5f

#define BK  8
#define LDT 136   // smem row stride; 136 % 32 == 8

// ---------------- device scratch (no cudaMalloc allowed) ----------------
__device__ float g_emb[2L * NN * DD];                 // layers 1,2 (layer0 = input)
__device__ float g_fc[(long)NN * HH * DD];            // combined fc output (users;items)
__device__ float g_rst[(long)N_USER * HH * DD];       // GAT aggregation
__device__ float g_trans[(long)NN * DD];
__device__ float g_el[N_USER * HH];
__device__ float g_er[N_USER * HH];
__device__ int   g_emax[N_USER * HH];
__device__ float g_denom[N_USER * HH];
__device__ float g_e[E_UI_C * HH];
__device__ float g_ex[E_UI_C * HH];
__device__ float g_agg[(long)NN * DD];
__device__ float g_cnt[NN];
__device__ float g_coef[(long)TREL * E_T_C * MMEM];
__device__ float g_ncoef[(long)NN * MMEM];
__device__ float g_tmp[(long)TREL * E_T_C * MMEM * DD];

// ---------------- helpers ----------------
__device__ __forceinline__ float lrelu(float x) { return x > 0.f ? x : 0.2f * x; }
__device__ __forceinline__ float eluf(float x)  { return x > 0.f ? x : expm1f(x); }
__device__ __forceinline__ int   encf(float f)  { int i = __float_as_int(f); return i >= 0 ? i : (i ^ 0x7FFFFFFF); }
__device__ __forceinline__ float decf(int i)    { return __int_as_float(i >= 0 ? i : (i ^ 0x7FFFFFFF)); }

__device__ __forceinline__ unsigned f2tf(float x) {
    unsigned u;
    asm("cvt.rna.tf32.f32 %0, %1;" : "=r"(u) : "f"(x));
    return u;
}

__device__ __forceinline__ void mma8(float* d, const unsigned* a, const unsigned* b) {
    asm("mma.sync.aligned.m16n8k8.row.col.f32.tf32.tf32.f32 "
        "{%0,%1,%2,%3}, {%4,%5,%6,%7}, {%8,%9}, {%0,%1,%2,%3};"
        : "+f"(d[0]), "+f"(d[1]), "+f"(d[2]), "+f"(d[3])
        : "r"(a[0]), "r"(a[1]), "r"(a[2]), "r"(a[3]), "r"(b[0]), "r"(b[1]));
}

// ---------------- 3xTF32 tensor-core GEMM: C = act(A[M,K] @ B[N,K]^T) ----------------
// Block tile 128x128xBK8; 8 warps = 2(m) x 4(n); warp tile 64x32 (4x4 m16n8k8 atoms).
// DOUBLE-BUFFERED smem (fits 48KB at BK=8): one __syncthreads per K-tile; storeS of the
// next tile overlaps the current tile's MMAs. In-loop hi/lo split; frags cached across
// the 3 TF32 passes.
// ACT: 0 plain, 1 elu(x + colBias), 2 plain store + fused attention dot (head = blockIdx.x).
// ATR: elu(a + aBias[k]) applied to A during load. GATHER: row-gather A via gidx.
template<int ACT, int ATR, int GATHER>
__global__ void __launch_bounds__(256, 2) gemm_tc(
    const float* __restrict__ A, int lda,
    const float* __restrict__ B, long strideB,
    float* __restrict__ C, int ldc, long strideC,
    const float* __restrict__ colBias,
    const float* __restrict__ aBias,
    const float* __restrict__ attnLo, float* __restrict__ outLo,
    const float* __restrict__ attnHi, float* __restrict__ outHi,
    const int* __restrict__ gidx, int strideIdx,
    int Mm, int Nn, int Kk)
{
    __shared__ float sAh[2][BK * LDT], sAl[2][BK * LDT];
    __shared__ float sBh[2][BK * LDT], sBl[2][BK * LDT];

    int z = blockIdx.z;
    B += (long)z * strideB;
    C += (long)z * strideC;
    const int* gptr = GATHER ? (gidx + (long)z * strideIdx) : nullptr;

    int tid = threadIdx.x;
    int lane = tid & 31, warp = tid >> 5;
    int warp_m = warp >> 2, warp_n = warp & 3;
    int q = lane >> 2, t4 = lane & 3;
    int row0 = blockIdx.y * 128;
    int col0 = blockIdx.x * 128;

    // staging map: each thread owns one float4 of A and one of B per tile
    int rS = tid >> 1;          // 0..127 (row / col)
    int c4 = tid & 1;           // k-offset group: k = c4*4 + j

    float acc[4][4][4];
    #pragma unroll
    for (int i = 0; i < 4; i++)
        #pragma unroll
        for (int j = 0; j < 4; j++)
            #pragma unroll
            for (int k = 0; k < 4; k++) acc[i][j][k] = 0.f;

    float4 aR, bR;

    auto loadG = [&](int k0) {
        int gr = row0 + rS;
        float4 v = make_float4(0.f, 0.f, 0.f, 0.f);
        if (gr < Mm) {
            long ar = GATHER ? (long)gptr[gr] : (long)gr;
            v = *reinterpret_cast<const float4*>(&A[ar * lda + k0 + c4 * 4]);
            if (ATR) {
                float4 b4 = *reinterpret_cast<const float4*>(&aBias[k0 + c4 * 4]);
                v.x = eluf(v.x + b4.x); v.y = eluf(v.y + b4.y);
                v.z = eluf(v.z + b4.z); v.w = eluf(v.w + b4.w);
            }
        }
        aR = v;
        bR = *reinterpret_cast<const float4*>(&B[(long)(col0 + rS) * Kk + k0 + c4 * 4]);
    };
    auto storeS = [&](int buf) {
        float va[4] = {aR.x, aR.y, aR.z, aR.w};
        float vb[4] = {bR.x, bR.y, bR.z, bR.w};
        #pragma unroll
        for (int j = 0; j < 4; j++) {
            int kr = c4 * 4 + j;
            float hi = __uint_as_float(f2tf(va[j]));
            sAh[buf][kr * LDT + rS] = hi;
            sAl[buf][kr * LDT + rS] = __uint_as_float(f2tf(va[j] - hi));
            float bhi = __uint_as_float(f2tf(vb[j]));
            sBh[buf][kr * LDT + rS] = bhi;
            sBl[buf][kr * LDT + rS] = __uint_as_float(f2tf(vb[j] - bhi));
        }
    };

    int nk = Kk / BK;
    loadG(0); storeS(0); __syncthreads();

    for (int kt = 0; kt < nk; kt++) {
        int cur = kt & 1;
        if (kt + 1 < nk) loadG((kt + 1) * BK);

        int kk = t4;
        unsigned bfh[4][2], bfl[4][2];
        #pragma unroll
        for (int na = 0; na < 4; na++) {
            int cw = warp_n * 32 + na * 8 + q;
            bfh[na][0] = __float_as_uint(sBh[cur][kk * LDT + cw]);
            bfh[na][1] = __float_as_uint(sBh[cur][(kk + 4) * LDT + cw]);
            bfl[na][0] = __float_as_uint(sBl[cur][kk * LDT + cw]);
            bfl[na][1] = __float_as_uint(sBl[cur][(kk + 4) * LDT + cw]);
        }
        #pragma unroll
        for (int mp = 0; mp < 2; mp++) {
            unsigned afh[2][4], afl[2][4];
            #pragma unroll
            for (int mi = 0; mi < 2; mi++) {
                int rw = warp_m * 64 + (mp * 2 + mi) * 16 + q;
                afh[mi][0] = __float_as_uint(sAh[cur][kk * LDT + rw]);
                afh[mi][1] = __float_as_uint(sAh[cur][kk * LDT + rw + 8]);
                afh[mi][2] = __float_as_uint(sAh[cur][(kk + 4) * LDT + rw]);
                afh[mi][3] = __float_as_uint(sAh[cur][(kk + 4) * LDT + rw + 8]);
                afl[mi][0] = __float_as_uint(sAl[cur][kk * LDT + rw]);
                afl[mi][1] = __float_as_uint(sAl[cur][kk * LDT + rw + 8]);
                afl[mi][2] = __float_as_uint(sAl[cur][(kk + 4) * LDT + rw]);
                afl[mi][3] = __float_as_uint(sAl[cur][(kk + 4) * LDT + rw + 8]);
            }
            #pragma unroll
            for (int mi = 0; mi < 2; mi++)
                #pragma unroll
                for (int na = 0; na < 4; na++) {
                    float* d = acc[mp * 2 + mi][na];
                    mma8(d, afh[mi], bfh[na]);
                    mma8(d, afh[mi], bfl[na]);
                    mma8(d, afl[mi], bfh[na]);
                }
        }

        if (kt + 1 < nk) storeS(cur ^ 1);   // other buffer: no barrier needed before
        __syncthreads();                     // one sync per tile
    }

    // ---- epilogue: store C ----
    #pragma unroll
    for (int ma = 0; ma < 4; ma++) {
        #pragma unroll
        for (int h = 0; h < 2; h++) {
            int r = row0 + warp_m * 64 + ma * 16 + q + 8 * h;
            if (r >= Mm) continue;
            #pragma unroll
            for (int na = 0; na < 4; na++) {
                int c = col0 + warp_n * 32 + na * 8 + t4 * 2;
                float v0 = acc[ma][na][2 * h], v1 = acc[ma][na][2 * h + 1];
                if (ACT == 1) {
                    v0 = eluf(v0 + colBias[c]);
                    v1 = eluf(v1 + colBias[c + 1]);
                }
                *reinterpret_cast<float2*>(&C[(long)r * ldc + c]) = make_float2(v0, v1);
            }
        }
    }

    // ---- fused attention dot (fc GEMM): cross-warp smem reduce ----
    if (ACT == 2) {
        float* sRed = sAh[0];
        #pragma unroll
        for (int ma = 0; ma < 4; ma++) {
            #pragma unroll
            for (int h = 0; h < 2; h++) {
                int rl = warp_m * 64 + ma * 16 + q + 8 * h;
                int r = row0 + rl;
                const float* av = (r < N_USER) ? attnLo : attnHi;
                float p = 0.f;
                #pragma unroll
                for (int na = 0; na < 4; na++) {
                    int c = col0 + warp_n * 32 + na * 8 + t4 * 2;
                    p += acc[ma][na][2 * h] * av[c] + acc[ma][na][2 * h + 1] * av[c + 1];
                }
                p += __shfl_xor_sync(0xffffffffu, p, 1);
                p += __shfl_xor_sync(0xffffffffu, p, 2);
                if (t4 == 0) sRed[rl * 4 + warp_n] = p;
            }
        }
        __syncthreads();
        if (tid < 128) {
            int r = row0 + tid;
            if (r < Mm) {
                float p = sRed[tid * 4] + sRed[tid * 4 + 1] + sRed[tid * 4 + 2] + sRed[tid * 4 + 3];
                int head = blockIdx.x;
                if (r < N_USER) outLo[r * HH + head] = p;
                else            outHi[(r - N_USER) * HH + head] = p;
            }
        }
    }
}

// ---------------- small kernels (unchanged, proven) ----------------
__global__ void zero_gat() {
    long i = (long)blockIdx.x * 256 + threadIdx.x;
    if (i < (long)N_USER * 512) g_rst[i] = 0.f;
    if (i < N_USER * HH) { g_emax[i] = INT_MIN; g_denom[i] = 0.f; }
}

__global__ void mem_init() {
    long i = (long)blockIdx.x * 256 + threadIdx.x;
    if (i < (long)NN * DD) g_agg[i] = 0.f;
    if (i < NN) g_cnt[i] = 0.f;
}

__global__ void gat_edge1(const int* __restrict__ s, const int* __restrict__ d) {
    int i = blockIdx.x * blockDim.x + threadIdx.x;
    if (i >= E_UI_C) return;
    int si = s[i], di = d[i];
    #pragma unroll
    for (int h = 0; h < HH; h++) {
        float e = lrelu(g_el[si * HH + h] + g_er[di * HH + h]);
        g_e[i * HH + h] = e;
        atomicMax(&g_emax[di * HH + h], encf(e));
    }
}

__global__ void gat_edge2(const int* __restrict__ d) {
    int i = blockIdx.x * blockDim.x + threadIdx.x;
    if (i >= E_UI_C) return;
    int di = d[i];
    #pragma unroll
    for (int h = 0; h < HH; h++) {
        float v = expf(g_e[i * HH + h] - decf(g_emax[di * HH + h]));
        g_ex[i * HH + h] = v;
        atomicAdd(&g_denom[di * HH + h], v);
    }
}

__global__ void gat_edge3(const int* __restrict__ s, const int* __restrict__ d,
                          const float* __restrict__ fs) {
    int sub = threadIdx.x >> 7;
    int e = blockIdx.x * 2 + sub;
    int t = threadIdx.x & 127;
    int si = s[e], di = d[e];
    int h = t >> 5;
    float a = g_ex[e * HH + h] / g_denom[di * HH + h];
    float4 f = *reinterpret_cast<const float4*>(&fs[(long)si * 512 + t * 4]);
    float* r = &g_rst[(long)di * 512 + t * 4];
    atomicAdd(r + 0, a * f.x); atomicAdd(r + 1, a * f.y);
    atomicAdd(r + 2, a * f.z); atomicAdd(r + 3, a * f.w);
}

__global__ void coef_kernel(const float* __restrict__ feat,
                            const int* __restrict__ idx, int idxStride,
                            const float* __restrict__ Wc, int WcStride,
                            const float* __restrict__ bc, int bcStride,
                            float* __restrict__ out, int count) {
    int z = blockIdx.y;
    __shared__ float sW[MMEM * DD];
    __shared__ float sb[MMEM];
    const float* W = Wc + (long)z * WcStride;
    for (int i = threadIdx.x; i < MMEM * DD; i += 256) sW[i] = W[i];
    if (threadIdx.x < MMEM) sb[threadIdx.x] = bc[z * bcStride + threadIdx.x];
    __syncthreads();
    int warp = threadIdx.x >> 5, lane = threadIdx.x & 31;
    int e = blockIdx.x * 8 + warp;
    if (e >= count) return;
    int node = idx ? idx[(long)z * idxStride + e] : e;
    const float* f = feat + (long)node * DD;
    float fv[4];
    #pragma unroll
    for (int j = 0; j < 4; j++) fv[j] = f[lane * 4 + j];
    #pragma unroll
    for (int m = 0; m < MMEM; m++) {
        float p = 0.f;
        #pragma unroll
        for (int j = 0; j < 4; j++) p += fv[j] * sW[m * DD + lane * 4 + j];
        #pragma unroll
        for (int o = 16; o; o >>= 1) p += __shfl_xor_sync(0xffffffffu, p, o);
        if (lane == 0) out[((long)z * count + e) * MMEM + m] = lrelu(p + sb[m]);
    }
}

__global__ void rel_reduce(const int* __restrict__ edst) {
    int warp = threadIdx.x >> 5, lane = threadIdx.x & 31;
    int e = blockIdx.x * 8 + warp;
    int t = blockIdx.y;
    long ei = (long)t * E_T_C + e;
    int dd = edst[ei];
    float c = lane < MMEM ? g_coef[ei * MMEM + lane] : 0.f;
    const float* tp = g_tmp + ei * (MMEM * DD);
    float4 s = make_float4(0.f, 0.f, 0.f, 0.f);
    #pragma unroll
    for (int m = 0; m < MMEM; m++) {
        float cm = __shfl_sync(0xffffffffu, c, m);
        float4 v = *reinterpret_cast<const float4*>(&tp[m * DD + lane * 4]);
        s.x += cm * v.x; s.y += cm * v.y; s.z += cm * v.z; s.w += cm * v.w;
    }
    float* ag = &g_agg[(long)dd * DD + lane * 4];
    atomicAdd(ag + 0, s.x); atomicAdd(ag + 1, s.y);
    atomicAdd(ag + 2, s.z); atomicAdd(ag + 3, s.w);
    if (lane == 0) atomicAdd(&g_cnt[dd], 1.0f);
}

__global__ void mem_finalize(const float* __restrict__ lnw, const float* __restrict__ lnb,
                             const float* __restrict__ hb, float* __restrict__ out) {
    int warp = threadIdx.x >> 5, lane = threadIdx.x & 31;
    int n = blockIdx.x * 8 + warp;
    float inv = 1.f / fmaxf(g_cnt[n], 1.f);
    float4 a = *reinterpret_cast<const float4*>(&g_agg[(long)n * DD + lane * 4]);
    a.x *= inv; a.y *= inv; a.z *= inv; a.w *= inv;
    float s = a.x + a.y + a.z + a.w;
    #pragma unroll
    for (int o = 16; o; o >>= 1) s += __shfl_xor_sync(0xffffffffu, s, o);
    float mu = s * (1.f / 128.f);
    float4 dv = make_float4(a.x - mu, a.y - mu, a.z - mu, a.w - mu);
    float vs = dv.x * dv.x + dv.y * dv.y + dv.z * dv.z + dv.w * dv.w;
    #pragma unroll
    for (int o = 16; o; o >>= 1) vs += __shfl_xor_sync(0xffffffffu, vs, o);
    float rs = rsqrtf(vs * (1.f / 128.f) + FEPS);
    float4 w4 = *reinterpret_cast<const float4*>(&lnw[lane * 4]);
    float4 b4 = *reinterpret_cast<const float4*>(&lnb[lane * 4]);
    float4 h4 = *reinterpret_cast<const float4*>(&hb[lane * 4]);
    float4 rep;
    rep.x = dv.x * rs * w4.x + b4.x + h4.x;
    rep.y = dv.y * rs * w4.y + b4.y + h4.y;
    rep.z = dv.z * rs * w4.z + b4.z + h4.z;
    rep.w = dv.w * rs * w4.w + b4.w + h4.w;
    float c = lane < MMEM ? g_ncoef[(long)n * MMEM + lane] : 0.f;
    const float* tp = g_tmp + (long)n * (MMEM * DD);
    float4 acc = make_float4(0.f, 0.f, 0.f, 0.f);
    #pragma unroll
    for (int m = 0; m < MMEM; m++) {
        float cm = __shfl_sync(0xffffffffu, c, m);
        float4 v = *reinterpret_cast<const float4*>(&tp[m * DD + lane * 4]);
        acc.x += cm * v.x; acc.y += cm * v.y; acc.z += cm * v.z; acc.w += cm * v.w;
    }
    float4 tr = *reinterpret_cast<const float4*>(&g_trans[(long)n * DD + lane * 4]);
    float4 o4;
    o4.x = lrelu(rep.x + acc.x) + tr.x;
    o4.y = lrelu(rep.y + acc.y) + tr.y;
    o4.z = lrelu(rep.z + acc.z) + tr.z;
    o4.w = lrelu(rep.w + acc.w) + tr.w;
    *reinterpret_cast<float4*>(&out[(long)n * DD + lane * 4]) = o4;
}

__global__ void final_ln_kernel(const float* __restrict__ e0,
                                const float* __restrict__ w, const float* __restrict__ b,
                                float* __restrict__ out) {
    int warp = threadIdx.x >> 5, lane = threadIdx.x & 31;
    int n = blockIdx.x * 8 + warp;
    float4 v0 = *reinterpret_cast<const float4*>(&e0[(long)n * DD + lane * 4]);
    float4 v1 = *reinterpret_cast<const float4*>(&g_emb[(long)n * DD + lane * 4]);
    float4 v2 = *reinterpret_cast<const float4*>(&g_emb[(long)NN * DD + (long)n * DD + lane * 4]);
    float s = v0.x + v0.y + v0.z + v0.w + v1.x + v1.y + v1.z + v1.w + v2.x + v2.y + v2.z + v2.w;
    #pragma unroll
    for (int o = 16; o; o >>= 1) s += __shfl_xor_sync(0xffffffffu, s, o);
    float mu = s * (1.f / 384.f);
    float4 d0 = make_float4(v0.x - mu, v0.y - mu, v0.z - mu, v0.w - mu);
    float4 d1 = make_float4(v1.x - mu, v1.y - mu, v1.z - mu, v1.w - mu);
    float4 d2 = make_float4(v2.x - mu, v2.y - mu, v2.z - mu, v2.w - mu);
    float vs = d0.x * d0.x + d0.y * d0.y + d0.z * d0.z + d0.w * d0.w
             + d1.x * d1.x + d1.y * d1.y + d1.z * d1.z + d1.w * d1.w
             + d2.x * d2.x + d2.y * d2.y + d2.z * d2.z + d2.w * d2.w;
    #pragma unroll
    for (int o = 16; o; o >>= 1) vs += __shfl_xor_sync(0xffffffffu, vs, o);
    float r = rsqrtf(vs * (1.f / 384.f) + FEPS);
    long base = (long)n * 384;
    #pragma unroll
    for (int seg = 0; seg < 3; seg++) {
        float4 d = seg == 0 ? d0 : (seg == 1 ? d1 : d2);
        int off = seg * 128 + lane * 4;
        float4 w4 = *reinterpret_cast<const float4*>(&w[off]);
        float4 b4 = *reinterpret_cast<const float4*>(&b[off]);
        float4 o4;
        o4.x = d.x * r * w4.x + b4.x; o4.y = d.y * r * w4.y + b4.y;
        o4.z = d.z * r * w4.z + b4.z; o4.w = d.w * r * w4.w + b4.w;
        *reinterpret_cast<float4*>(&out[base + off]) = o4;
    }
}

// ---------------- host orchestration ----------------
extern "C" void kernel_launch(void* const* d_in, const int* in_sizes, int n_in,
                              void* d_out, int out_size) {
    const float* embedding   = (const float*)d_in[0];
    const float* gat_fc_W    = (const float*)d_in[1];
    const float* gat_attn_l  = (const float*)d_in[2];
    const float* gat_attn_r  = (const float*)d_in[3];
    const float* gat_bias    = (const float*)d_in[4];
    const float* proj_W      = (const float*)d_in[5];
    const float* proj_b      = (const float*)d_in[6];
    const float* mem_rel_Wc  = (const float*)d_in[7];
    const float* mem_rel_bc  = (const float*)d_in[8];
    const float* mem_rel_Ww  = (const float*)d_in[9];
    const float* mem_node_Wc = (const float*)d_in[10];
    const float* mem_node_bc = (const float*)d_in[11];
    const float* mem_node_Ww = (const float*)d_in[12];
    const float* mem_h_bias  = (const float*)d_in[13];
    const float* mem_ln_w    = (const float*)d_in[14];
    const float* mem_ln_b    = (const float*)d_in[15];
    const float* final_ln_w  = (const float*)d_in[16];
    const float* final_ln_b  = (const float*)d_in[17];
    const int*   src_u       = (const int*)d_in[18];
    const int*   dst_i       = (const int*)d_in[19];
    const int*   edge_src    = (const int*)d_in[20];
    const int*   edge_dst    = (const int*)d_in[21];

    float *emb, *fc, *rst, *trans, *el, *er, *tmp, *coefp, *ncoefp;
    cudaGetSymbolAddress((void**)&emb,    g_emb);
    cudaGetSymbolAddress((void**)&fc,     g_fc);
    cudaGetSymbolAddress((void**)&rst,    g_rst);
    cudaGetSymbolAddress((void**)&trans,  g_trans);
    cudaGetSymbolAddress((void**)&el,     g_el);
    cudaGetSymbolAddress((void**)&er,     g_er);
    cudaGetSymbolAddress((void**)&tmp,    g_tmp);
    cudaGetSymbolAddress((void**)&coefp,  g_coef);
    cudaGetSymbolAddress((void**)&ncoefp, g_ncoef);

    for (int l = 0; l < LLAYERS; l++) {
        const float* fl = (l == 0) ? embedding : (emb + (long)(l - 1) * NN * DD);
        float* flout = emb + (long)l * NN * DD;

        for (int s = 0; s < 2; s++) {
            const float* W  = gat_fc_W   + ((long)l * 2 + s) * 512 * 128;
            const float* al = gat_attn_l + ((long)l * 2 + s) * 512;
            const float* ar = gat_attn_r + ((long)l * 2 + s) * 512;
            const float* gb = gat_bias   + ((long)l * 2 + s) * 512;
            const float* pW = proj_W     + ((long)l * 2 + s) * 128 * 512;
            const float* pb = proj_b     + ((long)l * 2 + s) * 128;
            // s=0: src=items(high rows), dst=users(low); s=1: src=users(low), dst=items(high)
            const float* vecLo = (s == 0) ? ar : al;
            float*       outLo = (s == 0) ? er : el;
            const float* vecHi = (s == 0) ? al : ar;
            float*       outHi = (s == 0) ? el : er;
            const int* sidx = (s == 0) ? dst_i : src_u;
            const int* didx = (s == 0) ? src_u : dst_i;
            const float* fsp = (s == 0) ? fc + (long)N_USER * 512 : fc;

            zero_gat<<<(N_USER * 512 + 255) / 256, 256>>>();
            dim3 gfc(4, (NN + 127) / 128, 1);
            gemm_tc<2, 0, 0><<<gfc, 256>>>(fl, DD, W, 0, fc, 512, 0,
                                           nullptr, nullptr,
                                           vecLo, outLo, vecHi, outHi,
                                           nullptr, 0, NN, 512, DD);
            gat_edge1<<<(E_UI_C + 255) / 256, 256>>>(sidx, didx);
            gat_edge2<<<(E_UI_C + 255) / 256, 256>>>(didx);
            gat_edge3<<<E_UI_C / 2, 256>>>(sidx, didx, fsp);
            float* Cp = trans + (long)s * N_USER * DD;
            dim3 gp(1, (N_USER + 127) / 128, 1);
            gemm_tc<1, 1, 0><<<gp, 256>>>(rst, 512, pW, 0, Cp, DD, 0,
                                          pb, gb,
                                          nullptr, nullptr, nullptr, nullptr,
                                          nullptr, 0, N_USER, DD, 512);
        }

        // -------- memory layer --------
        mem_init<<<(NN * DD + 255) / 256, 256>>>();
        dim3 gc((E_T_C + 7) / 8, TREL);
        coef_kernel<<<gc, 256>>>(fl, edge_dst, E_T_C,
                                 mem_rel_Wc + (long)l * TREL * MMEM * DD, MMEM * DD,
                                 mem_rel_bc + (long)l * TREL * MMEM, MMEM,
                                 coefp, E_T_C);
        dim3 gr(8, E_T_C / 128, TREL);
        gemm_tc<0, 0, 1><<<gr, 256>>>(fl, DD,
                                      mem_rel_Ww + (long)l * TREL * MMEM * DD * DD,
                                      (long)MMEM * DD * DD,
                                      tmp, MMEM * DD, (long)E_T_C * MMEM * DD,
                                      nullptr, nullptr,
                                      nullptr, nullptr, nullptr, nullptr,
                                      edge_src, E_T_C, E_T_C, MMEM * DD, DD);
        dim3 gs((E_T_C + 7) / 8, TREL);
        rel_reduce<<<gs, 256>>>(edge_dst);

        dim3 gnc((NN + 7) / 8, 1);
        coef_kernel<<<gnc, 256>>>(fl, nullptr, 0,
                                  mem_node_Wc + (long)l * MMEM * DD, 0,
                                  mem_node_bc + (long)l * MMEM, 0,
                                  ncoefp, NN);
        dim3 gn(8, (NN + 127) / 128, 1);
        gemm_tc<0, 0, 0><<<gn, 256>>>(fl, DD,
                                      mem_node_Ww + (long)l * MMEM * DD * DD, 0,
                                      tmp, MMEM * DD, 0,
                                      nullptr, nullptr,
                                      nullptr, nullptr, nullptr, nullptr,
                                      nullptr, 0, NN, MMEM * DD, DD);
        mem_finalize<<<NN / 8, 256>>>(mem_ln_w + l * DD, mem_ln_b + l * DD,
                                      mem_h_bias + l * DD, flout);
    }

    final_ln_kernel<<<NN / 8, 256>>>(embedding, final_ln_w, final_ln_b, (float*)d_out);
}